// round 5
// baseline (speedup 1.0000x reference)
#include <cuda_runtime.h>
#include <stdint.h>
#include <math.h>

#define B 8
#define S 4194304              // elements per sample (64*256*256)
#define WPS (S / 32)           // visibility words per sample
#define NR 5                   // ranks: med, q25lo, q25hi, q75lo, q75hi
#define NBLK 128               // K1 blocks per sample == compact regions
#define REG 32768              // elements per region (S/NBLK)

// ---------------- device scratch (static; no allocations) ----------------
static __device__ float    g_cmp[(size_t)B * S];   // compacted visible values (ragged regions)
static __device__ unsigned g_visbits[B * WPS];     // 4 MB: bit=1 -> visible
static __device__ int      g_bcnt[B][NBLK];
static __device__ int      g_n[B];
static __device__ int      g_hist0[B][4096];
static __device__ int      g_hist1[B][NR][4096];
static __device__ int      g_hist2[B][NR][256];
static __device__ unsigned g_prefix[B * NR];
static __device__ int      g_rem[B * NR];
static __device__ float    g_frac[B][2];
static __device__ float    g_med[B];
static __device__ float    g_q25[B], g_q75[B];
static __device__ int      g_mhist0[B][2048];
static __device__ int      g_mhist1[B][4096];
static __device__ int      g_mhist2[B][256];
static __device__ unsigned g_mprefix[B];
static __device__ int      g_mrem[B];
static __device__ float    g_scale[B];
static __device__ double   g_lsum;
static __device__ double   g_nmask;

__device__ __forceinline__ unsigned f2key(float x) {
    unsigned u = __float_as_uint(x);
    return (u & 0x80000000u) ? ~u : (u | 0x80000000u);
}
__device__ __forceinline__ float key2f(unsigned k) {
    unsigned u = (k & 0x80000000u) ? (k & 0x7FFFFFFFu) : ~k;
    return __uint_as_float(u);
}

// warp-aggregated shared-hist add; ALL 32 lanes must execute this (bin=~0u to skip)
__device__ __forceinline__ void whist_add(int* sh, unsigned bin) {
    unsigned peers = __match_any_sync(0xFFFFFFFFu, bin);
    if (bin != 0xFFFFFFFFu) {
        int leader = __ffs(peers) - 1;
        if ((int)(threadIdx.x & 31) == leader) atomicAdd(&sh[bin], __popc(peers));
    }
}

// ---------------- K0: zero histograms ----------------
__global__ void k0_zero() {
    int tid = blockIdx.x * blockDim.x + threadIdx.x;
    int st = gridDim.x * blockDim.x;
    int* p;
    p = (int*)g_hist0;  for (int i = tid; i < B * 4096;      i += st) p[i] = 0;
    p = (int*)g_hist1;  for (int i = tid; i < B * NR * 4096; i += st) p[i] = 0;
    p = (int*)g_hist2;  for (int i = tid; i < B * NR * 256;  i += st) p[i] = 0;
    p = (int*)g_mhist0; for (int i = tid; i < B * 2048;      i += st) p[i] = 0;
    p = (int*)g_mhist1; for (int i = tid; i < B * 4096;      i += st) p[i] = 0;
    p = (int*)g_mhist2; for (int i = tid; i < B * 256;       i += st) p[i] = 0;
    if (tid == 0) g_lsum = 0.0;
}

// ---------------- K1: compact + visbits + 12-bit hist ----------------
// grid (NBLK, B), block 256.
__global__ void __launch_bounds__(256) k1_compact(const float* __restrict__ tgt,
                                                   const float* __restrict__ msk) {
    __shared__ int sh[4096];
    __shared__ int blkpos;
    const int s = blockIdx.y;
    for (int i = threadIdx.x; i < 4096; i += 256) sh[i] = 0;
    if (threadIdx.x == 0) blkpos = 0;
    __syncthreads();

    const size_t soff = (size_t)s * S;
    const float* t = tgt + soff;
    const float* m = msk + soff;
    float* outv = g_cmp + soff + (size_t)blockIdx.x * REG;
    unsigned* vb = g_visbits + s * WPS;
    const int base = blockIdx.x * REG;
    const int lane = threadIdx.x & 31;

    for (int k = 0; k < 32; k++) {
        const int idx = base + k * 1024 + threadIdx.x * 4;
        const float4 mv = *reinterpret_cast<const float4*>(m + idx);
        const float4 tv = *reinterpret_cast<const float4*>(t + idx);
        const float mm[4] = {mv.x, mv.y, mv.z, mv.w};
        const float tt[4] = {tv.x, tv.y, tv.z, tv.w};
        unsigned vm = 0;
#pragma unroll
        for (int j = 0; j < 4; j++) if (mm[j] < 1.0f) vm |= 1u << j;  // visible <=> clip(m) < 1

        // aggregated histogram (all lanes converged here)
#pragma unroll
        for (int j = 0; j < 4; j++)
            whist_add(sh, (vm & (1u << j)) ? (f2key(tt[j]) >> 20) : 0xFFFFFFFFu);

        // assemble 32-bit visibility word across 8 consecutive lanes
        unsigned part = vm << (4 * (lane & 7));
        part |= __shfl_xor_sync(0xFFFFFFFFu, part, 1);
        part |= __shfl_xor_sync(0xFFFFFFFFu, part, 2);
        part |= __shfl_xor_sync(0xFFFFFFFFu, part, 4);
        if ((lane & 7) == 0) vb[idx >> 5] = part;

        // warp-aggregated compaction
        int vc = __popc(vm);
        int sc = vc;
#pragma unroll
        for (int d = 1; d < 32; d <<= 1) {
            int v = __shfl_up_sync(0xFFFFFFFFu, sc, d);
            if (lane >= d) sc += v;
        }
        int wtotal = __shfl_sync(0xFFFFFFFFu, sc, 31);
        int wbase = 0;
        if (lane == 0 && wtotal) wbase = atomicAdd(&blkpos, wtotal);
        wbase = __shfl_sync(0xFFFFFFFFu, wbase, 0);
        int o = wbase + sc - vc;
#pragma unroll
        for (int j = 0; j < 4; j++)
            if (vm & (1u << j)) outv[o++] = tt[j];
    }
    __syncthreads();
    if (threadIdx.x == 0) g_bcnt[s][blockIdx.x] = blkpos;
    for (int i = threadIdx.x; i < 4096; i += 256)
        if (sh[i]) atomicAdd(&g_hist0[s][i], sh[i]);
}

// ---------------- block-parallel scan + rank-find helper ----------------
template <int NB>
__device__ __forceinline__ void scan_find_one(const int* __restrict__ h,
                                              unsigned* pf, int* rem, int shift) {
    constexpr int C = NB / 256;
    const int tid = threadIdx.x, lane = tid & 31, w = tid >> 5;
    __shared__ int wtot[8];
    int c[C]; int tot = 0;
#pragma unroll
    for (int i = 0; i < C; i++) { c[i] = h[tid * C + i]; tot += c[i]; }
    int sc = tot;
#pragma unroll
    for (int d = 1; d < 32; d <<= 1) {
        int v = __shfl_up_sync(0xFFFFFFFFu, sc, d);
        if (lane >= d) sc += v;
    }
    if (lane == 31) wtot[w] = sc;
    const int r = *rem;          // read BEFORE finder may overwrite
    __syncthreads();
    int woff = 0;
#pragma unroll
    for (int i = 0; i < 8; i++) if (i < w) woff += wtot[i];
    int prev = woff + sc - tot;
#pragma unroll
    for (int i = 0; i < C; i++) {
        if (prev <= r && r < prev + c[i]) {
            *pf = ((*pf) << shift) | (unsigned)(tid * C + i);
            *rem = r - prev;
        }
        prev += c[i];
    }
}

// ---------------- K2: ranks + level-0 scan (block per sample) ----------------
__global__ void k2_setup() {
    const int s = blockIdx.x, tid = threadIdx.x, lane = tid & 31, w = tid >> 5;
    __shared__ int wtot[8];
    int c[16]; int tot = 0;
    const int* h = g_hist0[s];
#pragma unroll
    for (int i = 0; i < 16; i++) { c[i] = h[tid * 16 + i]; tot += c[i]; }
    int sc = tot;
#pragma unroll
    for (int d = 1; d < 32; d <<= 1) {
        int v = __shfl_up_sync(0xFFFFFFFFu, sc, d);
        if (lane >= d) sc += v;
    }
    if (lane == 31) wtot[w] = sc;
    __syncthreads();
    int woff = 0, n = 0;
#pragma unroll
    for (int i = 0; i < 8; i++) { if (i < w) woff += wtot[i]; n += wtot[i]; }
    int prev = woff + sc - tot;

    float nm1 = fmaxf((float)n - 1.0f, 0.0f);
    float p25 = 0.25f * nm1, p75 = 0.75f * nm1;
    float f25 = floorf(p25), f75 = floorf(p75);
    int r[NR];
    r[0] = (n > 0) ? (n - 1) / 2 : 0;
    r[1] = min(max((int)f25, 0), S - 1);
    r[2] = min(max((int)ceilf(p25), 0), S - 1);
    r[3] = min(max((int)f75, 0), S - 1);
    r[4] = min(max((int)ceilf(p75), 0), S - 1);
#pragma unroll
    for (int i = 0; i < 16; i++) {
#pragma unroll
        for (int j = 0; j < NR; j++)
            if (prev <= r[j] && r[j] < prev + c[i]) {
                g_prefix[s * NR + j] = (unsigned)(tid * 16 + i);
                g_rem[s * NR + j]    = r[j] - prev;
            }
        prev += c[i];
    }
    if (tid == 0) {
        g_n[s] = n;
        g_frac[s][0] = p25 - f25;
        g_frac[s][1] = p75 - f75;
        g_mprefix[s] = 0;
        g_mrem[s] = (n > 0) ? (n - 1) / 2 : 0;
        if (n == 0)
            for (int j = 0; j < NR; j++) { g_prefix[s * NR + j] = 0; g_rem[s * NR + j] = 0; }
    }
}

// ---------------- K3/K5: target refine over compact data (vectorized) ----------------
__global__ void __launch_bounds__(256) k3_ref1() {
    const int s = blockIdx.y, b = blockIdx.x;
    const int cnt = g_bcnt[s][b];
    const float* v = g_cmp + (size_t)s * S + (size_t)b * REG;
    const float4* v4 = reinterpret_cast<const float4*>(v);
    unsigned pf[NR];
#pragma unroll
    for (int j = 0; j < NR; j++) pf[j] = g_prefix[s * NR + j];
    const int nvec = cnt >> 2;
#pragma unroll 4
    for (int i = threadIdx.x; i < nvec; i += 256) {
        const float4 x = v4[i];
        const float xx[4] = {x.x, x.y, x.z, x.w};
#pragma unroll
        for (int e = 0; e < 4; e++) {
            unsigned key = f2key(xx[e]);
            unsigned top = key >> 20;
#pragma unroll
            for (int j = 0; j < NR; j++)
                if (top == pf[j]) atomicAdd(&g_hist1[s][j][(key >> 8) & 0xFFF], 1);
        }
    }
    for (int i = (nvec << 2) + threadIdx.x; i < cnt; i += 256) {
        unsigned key = f2key(v[i]);
        unsigned top = key >> 20;
#pragma unroll
        for (int j = 0; j < NR; j++)
            if (top == pf[j]) atomicAdd(&g_hist1[s][j][(key >> 8) & 0xFFF], 1);
    }
}

__global__ void k4_scan1() {
    const int b = blockIdx.x;           // 0..B*NR-1
    const int s = b / NR;
    if (g_n[s] <= 0) return;
    scan_find_one<4096>(g_hist1[s][b % NR], &g_prefix[b], &g_rem[b], 12);
}

__global__ void __launch_bounds__(256) k5_ref2() {
    const int s = blockIdx.y, b = blockIdx.x;
    const int cnt = g_bcnt[s][b];
    const float* v = g_cmp + (size_t)s * S + (size_t)b * REG;
    const float4* v4 = reinterpret_cast<const float4*>(v);
    unsigned pf[NR];
#pragma unroll
    for (int j = 0; j < NR; j++) pf[j] = g_prefix[s * NR + j];  // 24-bit
    const int nvec = cnt >> 2;
#pragma unroll 4
    for (int i = threadIdx.x; i < nvec; i += 256) {
        const float4 x = v4[i];
        const float xx[4] = {x.x, x.y, x.z, x.w};
#pragma unroll
        for (int e = 0; e < 4; e++) {
            unsigned key = f2key(xx[e]);
            unsigned top = key >> 8;
#pragma unroll
            for (int j = 0; j < NR; j++)
                if (top == pf[j]) atomicAdd(&g_hist2[s][j][key & 0xFF], 1);
        }
    }
    for (int i = (nvec << 2) + threadIdx.x; i < cnt; i += 256) {
        unsigned key = f2key(v[i]);
        unsigned top = key >> 8;
#pragma unroll
        for (int j = 0; j < NR; j++)
            if (top == pf[j]) atomicAdd(&g_hist2[s][j][key & 0xFF], 1);
    }
}

// ---------------- K6: finalize med / q25 / q75 ----------------
__global__ void k6_vals() {
    __shared__ float vv[B][NR];
    const int tid = threadIdx.x;  // 256 threads, 1 block
    if (tid < B * NR) {
        const int s = tid / NR, j = tid % NR;
        float val = 0.0f;
        if (g_n[s] > 0) {
            int r = g_rem[tid], cum = 0;
            unsigned pf = g_prefix[tid];
            const int* h = g_hist2[s][j];
            for (int b2 = 0; b2 < 256; b2++) {
                int c = h[b2];
                if (r < cum + c) { val = key2f((pf << 8) | (unsigned)b2); break; }
                cum += c;
            }
        }
        vv[s][j] = val;
    }
    __syncthreads();
    if (tid < B) {
        const int s = tid;
        g_med[s] = (g_n[s] > 0) ? vv[s][0] : 0.0f;
        g_q25[s] = vv[s][1] + (vv[s][2] - vv[s][1]) * g_frac[s][0];
        g_q75[s] = vv[s][3] + (vv[s][4] - vv[s][3]) * g_frac[s][1];
    }
}

// ---------------- K7/K9/K11: MAD selection over compact data ----------------
__global__ void __launch_bounds__(256) k7_mhist0() {
    __shared__ int sh[2048];
    const int s = blockIdx.y, b = blockIdx.x;
    for (int i = threadIdx.x; i < 2048; i += 256) sh[i] = 0;
    __syncthreads();
    const float med = g_med[s];
    const int cnt = g_bcnt[s][b];
    const float* v = g_cmp + (size_t)s * S + (size_t)b * REG;
    const float4* v4 = reinterpret_cast<const float4*>(v);
    const int nvec = cnt >> 2;
    const int iters = (nvec + 255) >> 8;       // uniform loop count for warp convergence
    for (int k = 0; k < iters; k++) {
        const int i = k * 256 + threadIdx.x;
        float4 x = make_float4(0.f, 0.f, 0.f, 0.f);
        const bool ok = (i < nvec);
        if (ok) x = v4[i];
        const float xx[4] = {x.x, x.y, x.z, x.w};
#pragma unroll
        for (int e = 0; e < 4; e++)
            whist_add(sh, ok ? (__float_as_uint(fabsf(xx[e] - med)) >> 20) : 0xFFFFFFFFu);
    }
    for (int i = (nvec << 2) + threadIdx.x; i < cnt; i += 256)
        atomicAdd(&sh[__float_as_uint(fabsf(v[i] - med)) >> 20], 1);
    __syncthreads();
    for (int i = threadIdx.x; i < 2048; i += 256)
        if (sh[i]) atomicAdd(&g_mhist0[s][i], sh[i]);
}

__global__ void k8_mscan0() {
    const int s = blockIdx.x;
    if (g_n[s] <= 0) return;
    scan_find_one<2048>(g_mhist0[s], &g_mprefix[s], &g_mrem[s], 0);
}

__global__ void __launch_bounds__(256) k9_mref1() {
    const int s = blockIdx.y, b = blockIdx.x;
    const float med = g_med[s];
    const unsigned pf = g_mprefix[s];
    const int cnt = g_bcnt[s][b];
    const float* v = g_cmp + (size_t)s * S + (size_t)b * REG;
    const float4* v4 = reinterpret_cast<const float4*>(v);
    const int nvec = cnt >> 2;
#pragma unroll 4
    for (int i = threadIdx.x; i < nvec; i += 256) {
        const float4 x = v4[i];
        const float xx[4] = {x.x, x.y, x.z, x.w};
#pragma unroll
        for (int e = 0; e < 4; e++) {
            unsigned u = __float_as_uint(fabsf(xx[e] - med));
            if ((u >> 20) == pf) atomicAdd(&g_mhist1[s][(u >> 8) & 0xFFF], 1);
        }
    }
    for (int i = (nvec << 2) + threadIdx.x; i < cnt; i += 256) {
        unsigned u = __float_as_uint(fabsf(v[i] - med));
        if ((u >> 20) == pf) atomicAdd(&g_mhist1[s][(u >> 8) & 0xFFF], 1);
    }
}

__global__ void k10_mscan1() {
    const int s = blockIdx.x;
    if (g_n[s] <= 0) return;
    scan_find_one<4096>(g_mhist1[s], &g_mprefix[s], &g_mrem[s], 12);
}

__global__ void __launch_bounds__(256) k11_mref2() {
    const int s = blockIdx.y, b = blockIdx.x;
    const float med = g_med[s];
    const unsigned pf = g_mprefix[s];   // 24-bit
    const int cnt = g_bcnt[s][b];
    const float* v = g_cmp + (size_t)s * S + (size_t)b * REG;
    const float4* v4 = reinterpret_cast<const float4*>(v);
    const int nvec = cnt >> 2;
#pragma unroll 4
    for (int i = threadIdx.x; i < nvec; i += 256) {
        const float4 x = v4[i];
        const float xx[4] = {x.x, x.y, x.z, x.w};
#pragma unroll
        for (int e = 0; e < 4; e++) {
            unsigned u = __float_as_uint(fabsf(xx[e] - med));
            if ((u >> 8) == pf) atomicAdd(&g_mhist2[s][u & 0xFF], 1);
        }
    }
    for (int i = (nvec << 2) + threadIdx.x; i < cnt; i += 256) {
        unsigned u = __float_as_uint(fabsf(v[i] - med));
        if ((u >> 8) == pf) atomicAdd(&g_mhist2[s][u & 0xFF], 1);
    }
}

// ---------------- K12: final per-sample scalars + num_masked ----------------
__global__ void k12_final() {
    const int tid = threadIdx.x;  // 32 threads
    if (tid < B) {
        const int s = tid, n = g_n[s];
        float mad = 0.0f;
        if (n > 0) {
            int r = g_mrem[s], cum = 0;
            unsigned pf = g_mprefix[s];
            const int* h = g_mhist2[s];
            for (int b2 = 0; b2 < 256; b2++) {
                int c = h[b2];
                if (r < cum + c) { mad = __uint_as_float((pf << 8) | (unsigned)b2); break; }
                cum += c;
            }
        }
        float scaled = 1.4826f * mad;
        float iqr = fmaxf((g_q75[s] - g_q25[s]) / 1.35f, 1e-6f);
        float fm = (scaled < 0.1f) ? iqr : scaled;
        if (n <= 0) fm = 1.0f;
        int dn = (n > 0) && (fm > 0.1f);
        g_scale[s] = dn ? (1.0f / fm) : 1.0f;   // (p-med)/fm - (t-med)/fm == (p-t)/fm
    }
    if (tid == 0) {
        double nm = (double)B * (double)S;      // binary mask: sum(mask) = total - visible
        for (int s2 = 0; s2 < B; s2++) nm -= (double)g_n[s2];
        g_nmask = nm;
    }
}

// ---------------- K13: masked-MSE using visbits (no mask read) ----------------
// grid (512, B), block 256.
__global__ void __launch_bounds__(256) k13_loss(const float* __restrict__ pred,
                                                const float* __restrict__ tgt) {
    const int s = blockIdx.y;
    const float sc = g_scale[s];
    const size_t off = (size_t)s * S;
    const float* p = pred + off;
    const float* t = tgt + off;
    const unsigned* vb = g_visbits + s * WPS;
    const int base = blockIdx.x * 8192;
    float ls = 0.0f;
#pragma unroll
    for (int k = 0; k < 8; k++) {
        const int idx = base + k * 1024 + threadIdx.x * 4;
        const float4 pv = *reinterpret_cast<const float4*>(p + idx);
        const float4 tv = *reinterpret_cast<const float4*>(t + idx);
        const unsigned nib = (vb[idx >> 5] >> (idx & 31)) & 0xF;
        const float pp[4] = {pv.x, pv.y, pv.z, pv.w};
        const float tt[4] = {tv.x, tv.y, tv.z, tv.w};
#pragma unroll
        for (int j = 0; j < 4; j++) {
            float d = (pp[j] - tt[j]) * sc;
            float l = fminf(d * d, 100.0f);
            ls += ((nib >> j) & 1u) ? 0.0f : l;   // masked <=> not visible
        }
    }
    for (int o = 16; o; o >>= 1) ls += __shfl_down_sync(0xFFFFFFFFu, ls, o);
    __shared__ float wls[8];
    if ((threadIdx.x & 31) == 0) wls[threadIdx.x >> 5] = ls;
    __syncthreads();
    if (threadIdx.x == 0) {
        double a = 0.0;
        for (int i = 0; i < 8; i++) a += (double)wls[i];
        atomicAdd(&g_lsum, a);
    }
}

// ---------------- K14: write scalar output ----------------
__global__ void k14_out(float* out) {
    double nm = g_nmask;
    out[0] = (nm > 0.0) ? (float)(g_lsum / fmax(nm, 1.0)) : 0.0f;
}

// ---------------- launch ----------------
extern "C" void kernel_launch(void* const* d_in, const int* in_sizes, int n_in,
                              void* d_out, int out_size) {
    const float* pred = (const float*)d_in[0];
    const float* tgt  = (const float*)d_in[1];
    const float* msk  = (const float*)d_in[2];
    float* out = (float*)d_out;

    dim3 greg(NBLK, B), gloss(512, B);

    k0_zero<<<128, 256>>>();
    k1_compact<<<greg, 256>>>(tgt, msk);
    k2_setup<<<B, 256>>>();
    k3_ref1<<<greg, 256>>>();
    k4_scan1<<<B * NR, 256>>>();
    k5_ref2<<<greg, 256>>>();
    k6_vals<<<1, 256>>>();
    k7_mhist0<<<greg, 256>>>();
    k8_mscan0<<<B, 256>>>();
    k9_mref1<<<greg, 256>>>();
    k10_mscan1<<<B, 256>>>();
    k11_mref2<<<greg, 256>>>();
    k12_final<<<1, 32>>>();
    k13_loss<<<gloss, 256>>>(pred, tgt);
    k14_out<<<1, 1>>>(out);
}

// round 7
// speedup vs baseline: 1.3518x; 1.3518x over previous
#include <cuda_runtime.h>
#include <stdint.h>
#include <math.h>

#define B 8
#define S 4194304              // elements per sample (64*256*256)
#define WPS (S / 32)           // visibility words per sample
#define NR 5                   // ranks: med, q25lo, q25hi, q75lo, q75hi
#define NBLK 128               // K1 blocks per sample == compact regions
#define REG 32768              // elements per region (S/NBLK)

// ---------------- device scratch (static; no allocations) ----------------
static __device__ float    g_cmp[(size_t)B * S];   // compacted visible values (ragged regions)
static __device__ unsigned g_visbits[B * WPS];     // 4 MB: bit=1 -> visible
static __device__ int      g_bcnt[B][NBLK];
static __device__ int      g_n[B];
static __device__ int      g_hist0[B][4096];
static __device__ int      g_hist1[B][NR][4096];
static __device__ int      g_hist2[B][NR][256];
static __device__ unsigned g_prefix[B * NR];
static __device__ int      g_rem[B * NR];
static __device__ float    g_frac[B][2];
static __device__ float    g_med[B];
static __device__ float    g_q25[B], g_q75[B];
static __device__ int      g_mhist0[B][2048];
static __device__ int      g_mhist1[B][4096];
static __device__ int      g_mhist2[B][256];
static __device__ unsigned g_mprefix[B];
static __device__ int      g_mrem[B];
static __device__ float    g_scale[B];
static __device__ double   g_lsum;
static __device__ double   g_nmask;

__device__ __forceinline__ unsigned f2key(float x) {
    unsigned u = __float_as_uint(x);
    return (u & 0x80000000u) ? ~u : (u | 0x80000000u);
}
__device__ __forceinline__ float key2f(unsigned k) {
    unsigned u = (k & 0x80000000u) ? (k & 0x7FFFFFFFu) : ~k;
    return __uint_as_float(u);
}

// ---------------- K0: zero histograms ----------------
__global__ void k0_zero() {
    int tid = blockIdx.x * blockDim.x + threadIdx.x;
    int st = gridDim.x * blockDim.x;
    int* p;
    p = (int*)g_hist0;  for (int i = tid; i < B * 4096;      i += st) p[i] = 0;
    p = (int*)g_hist1;  for (int i = tid; i < B * NR * 4096; i += st) p[i] = 0;
    p = (int*)g_hist2;  for (int i = tid; i < B * NR * 256;  i += st) p[i] = 0;
    p = (int*)g_mhist0; for (int i = tid; i < B * 2048;      i += st) p[i] = 0;
    p = (int*)g_mhist1; for (int i = tid; i < B * 4096;      i += st) p[i] = 0;
    p = (int*)g_mhist2; for (int i = tid; i < B * 256;       i += st) p[i] = 0;
    if (tid == 0) g_lsum = 0.0;
}

// ---------------- K1: compact + visbits + 12-bit hist (plain atomics) ----------------
// grid (NBLK, B), block 256.
__global__ void __launch_bounds__(256) k1_compact(const float* __restrict__ tgt,
                                                   const float* __restrict__ msk) {
    __shared__ int sh[4096];
    __shared__ int blkpos;
    const int s = blockIdx.y;
    for (int i = threadIdx.x; i < 4096; i += 256) sh[i] = 0;
    if (threadIdx.x == 0) blkpos = 0;
    __syncthreads();

    const size_t soff = (size_t)s * S;
    const float* t = tgt + soff;
    const float* m = msk + soff;
    float* outv = g_cmp + soff + (size_t)blockIdx.x * REG;
    unsigned* vb = g_visbits + s * WPS;
    const int base = blockIdx.x * REG;
    const int lane = threadIdx.x & 31;

    for (int k = 0; k < 32; k++) {
        const int idx = base + k * 1024 + threadIdx.x * 4;
        const float4 mv = *reinterpret_cast<const float4*>(m + idx);
        const float4 tv = *reinterpret_cast<const float4*>(t + idx);
        const float mm[4] = {mv.x, mv.y, mv.z, mv.w};
        const float tt[4] = {tv.x, tv.y, tv.z, tv.w};
        unsigned vm = 0;
#pragma unroll
        for (int j = 0; j < 4; j++) if (mm[j] < 1.0f) vm |= 1u << j;  // visible <=> clip(m) < 1
#pragma unroll
        for (int j = 0; j < 4; j++)
            if (vm & (1u << j)) atomicAdd(&sh[f2key(tt[j]) >> 20], 1);

        // assemble 32-bit visibility word across 8 consecutive lanes
        unsigned part = vm << (4 * (lane & 7));
        part |= __shfl_xor_sync(0xFFFFFFFFu, part, 1);
        part |= __shfl_xor_sync(0xFFFFFFFFu, part, 2);
        part |= __shfl_xor_sync(0xFFFFFFFFu, part, 4);
        if ((lane & 7) == 0) vb[idx >> 5] = part;

        // warp-aggregated compaction
        int vc = __popc(vm);
        int sc = vc;
#pragma unroll
        for (int d = 1; d < 32; d <<= 1) {
            int v = __shfl_up_sync(0xFFFFFFFFu, sc, d);
            if (lane >= d) sc += v;
        }
        int wtotal = __shfl_sync(0xFFFFFFFFu, sc, 31);
        int wbase = 0;
        if (lane == 0 && wtotal) wbase = atomicAdd(&blkpos, wtotal);
        wbase = __shfl_sync(0xFFFFFFFFu, wbase, 0);
        int o = wbase + sc - vc;
#pragma unroll
        for (int j = 0; j < 4; j++)
            if (vm & (1u << j)) outv[o++] = tt[j];
    }
    __syncthreads();
    if (threadIdx.x == 0) g_bcnt[s][blockIdx.x] = blkpos;
    for (int i = threadIdx.x; i < 4096; i += 256)
        if (sh[i]) atomicAdd(&g_hist0[s][i], sh[i]);
}

// ---------------- block-parallel scan + rank-find helper ----------------
template <int NB>
__device__ __forceinline__ void scan_find_one(const int* __restrict__ h,
                                              unsigned* pf, int* rem, int shift) {
    constexpr int C = NB / 256;
    const int tid = threadIdx.x, lane = tid & 31, w = tid >> 5;
    __shared__ int wtot[8];
    int c[C]; int tot = 0;
#pragma unroll
    for (int i = 0; i < C; i++) { c[i] = h[tid * C + i]; tot += c[i]; }
    int sc = tot;
#pragma unroll
    for (int d = 1; d < 32; d <<= 1) {
        int v = __shfl_up_sync(0xFFFFFFFFu, sc, d);
        if (lane >= d) sc += v;
    }
    if (lane == 31) wtot[w] = sc;
    const int r = *rem;          // read BEFORE finder may overwrite
    __syncthreads();
    int woff = 0;
#pragma unroll
    for (int i = 0; i < 8; i++) if (i < w) woff += wtot[i];
    int prev = woff + sc - tot;
#pragma unroll
    for (int i = 0; i < C; i++) {
        if (prev <= r && r < prev + c[i]) {
            *pf = ((*pf) << shift) | (unsigned)(tid * C + i);
            *rem = r - prev;
        }
        prev += c[i];
    }
}

// ---------------- K2: ranks + level-0 scan (block per sample) ----------------
__global__ void k2_setup() {
    const int s = blockIdx.x, tid = threadIdx.x, lane = tid & 31, w = tid >> 5;
    __shared__ int wtot[8];
    int c[16]; int tot = 0;
    const int* h = g_hist0[s];
#pragma unroll
    for (int i = 0; i < 16; i++) { c[i] = h[tid * 16 + i]; tot += c[i]; }
    int sc = tot;
#pragma unroll
    for (int d = 1; d < 32; d <<= 1) {
        int v = __shfl_up_sync(0xFFFFFFFFu, sc, d);
        if (lane >= d) sc += v;
    }
    if (lane == 31) wtot[w] = sc;
    __syncthreads();
    int woff = 0, n = 0;
#pragma unroll
    for (int i = 0; i < 8; i++) { if (i < w) woff += wtot[i]; n += wtot[i]; }
    int prev = woff + sc - tot;

    float nm1 = fmaxf((float)n - 1.0f, 0.0f);
    float p25 = 0.25f * nm1, p75 = 0.75f * nm1;
    float f25 = floorf(p25), f75 = floorf(p75);
    int r[NR];
    r[0] = (n > 0) ? (n - 1) / 2 : 0;
    r[1] = min(max((int)f25, 0), S - 1);
    r[2] = min(max((int)ceilf(p25), 0), S - 1);
    r[3] = min(max((int)f75, 0), S - 1);
    r[4] = min(max((int)ceilf(p75), 0), S - 1);
#pragma unroll
    for (int i = 0; i < 16; i++) {
#pragma unroll
        for (int j = 0; j < NR; j++)
            if (prev <= r[j] && r[j] < prev + c[i]) {
                g_prefix[s * NR + j] = (unsigned)(tid * 16 + i);
                g_rem[s * NR + j]    = r[j] - prev;
            }
        prev += c[i];
    }
    if (tid == 0) {
        g_n[s] = n;
        g_frac[s][0] = p25 - f25;
        g_frac[s][1] = p75 - f75;
        g_mprefix[s] = 0;
        g_mrem[s] = (n > 0) ? (n - 1) / 2 : 0;
        if (n == 0)
            for (int j = 0; j < NR; j++) { g_prefix[s * NR + j] = 0; g_rem[s * NR + j] = 0; }
    }
}

// ---------------- K3/K5: target refine over compact data (vectorized) ----------------
__global__ void __launch_bounds__(256) k3_ref1() {
    const int s = blockIdx.y, b = blockIdx.x;
    const int cnt = g_bcnt[s][b];
    const float* v = g_cmp + (size_t)s * S + (size_t)b * REG;
    const float4* v4 = reinterpret_cast<const float4*>(v);
    unsigned pf[NR];
#pragma unroll
    for (int j = 0; j < NR; j++) pf[j] = g_prefix[s * NR + j];
    const int nvec = cnt >> 2;
#pragma unroll 4
    for (int i = threadIdx.x; i < nvec; i += 256) {
        const float4 x = v4[i];
        const float xx[4] = {x.x, x.y, x.z, x.w};
#pragma unroll
        for (int e = 0; e < 4; e++) {
            unsigned key = f2key(xx[e]);
            unsigned top = key >> 20;
#pragma unroll
            for (int j = 0; j < NR; j++)
                if (top == pf[j]) atomicAdd(&g_hist1[s][j][(key >> 8) & 0xFFF], 1);
        }
    }
    for (int i = (nvec << 2) + threadIdx.x; i < cnt; i += 256) {
        unsigned key = f2key(v[i]);
        unsigned top = key >> 20;
#pragma unroll
        for (int j = 0; j < NR; j++)
            if (top == pf[j]) atomicAdd(&g_hist1[s][j][(key >> 8) & 0xFFF], 1);
    }
}

__global__ void k4_scan1() {
    const int b = blockIdx.x;           // 0..B*NR-1
    const int s = b / NR;
    if (g_n[s] <= 0) return;
    scan_find_one<4096>(g_hist1[s][b % NR], &g_prefix[b], &g_rem[b], 12);
}

__global__ void __launch_bounds__(256) k5_ref2() {
    const int s = blockIdx.y, b = blockIdx.x;
    const int cnt = g_bcnt[s][b];
    const float* v = g_cmp + (size_t)s * S + (size_t)b * REG;
    const float4* v4 = reinterpret_cast<const float4*>(v);
    unsigned pf[NR];
#pragma unroll
    for (int j = 0; j < NR; j++) pf[j] = g_prefix[s * NR + j];  // 24-bit
    const int nvec = cnt >> 2;
#pragma unroll 4
    for (int i = threadIdx.x; i < nvec; i += 256) {
        const float4 x = v4[i];
        const float xx[4] = {x.x, x.y, x.z, x.w};
#pragma unroll
        for (int e = 0; e < 4; e++) {
            unsigned key = f2key(xx[e]);
            unsigned top = key >> 8;
#pragma unroll
            for (int j = 0; j < NR; j++)
                if (top == pf[j]) atomicAdd(&g_hist2[s][j][key & 0xFF], 1);
        }
    }
    for (int i = (nvec << 2) + threadIdx.x; i < cnt; i += 256) {
        unsigned key = f2key(v[i]);
        unsigned top = key >> 8;
#pragma unroll
        for (int j = 0; j < NR; j++)
            if (top == pf[j]) atomicAdd(&g_hist2[s][j][key & 0xFF], 1);
    }
}

// ---------------- K6: finalize med / q25 / q75 ----------------
__global__ void k6_vals() {
    __shared__ float vv[B][NR];
    const int tid = threadIdx.x;  // 256 threads, 1 block
    if (tid < B * NR) {
        const int s = tid / NR, j = tid % NR;
        float val = 0.0f;
        if (g_n[s] > 0) {
            int r = g_rem[tid], cum = 0;
            unsigned pf = g_prefix[tid];
            const int* h = g_hist2[s][j];
            for (int b2 = 0; b2 < 256; b2++) {
                int c = h[b2];
                if (r < cum + c) { val = key2f((pf << 8) | (unsigned)b2); break; }
                cum += c;
            }
        }
        vv[s][j] = val;
    }
    __syncthreads();
    if (tid < B) {
        const int s = tid;
        g_med[s] = (g_n[s] > 0) ? vv[s][0] : 0.0f;
        g_q25[s] = vv[s][1] + (vv[s][2] - vv[s][1]) * g_frac[s][0];
        g_q75[s] = vv[s][3] + (vv[s][4] - vv[s][3]) * g_frac[s][1];
    }
}

// ---------------- K7/K9/K11: MAD selection over compact data ----------------
__global__ void __launch_bounds__(256) k7_mhist0() {
    __shared__ int sh[2048];
    const int s = blockIdx.y, b = blockIdx.x;
    for (int i = threadIdx.x; i < 2048; i += 256) sh[i] = 0;
    __syncthreads();
    const float med = g_med[s];
    const int cnt = g_bcnt[s][b];
    const float* v = g_cmp + (size_t)s * S + (size_t)b * REG;
    const float4* v4 = reinterpret_cast<const float4*>(v);
    const int nvec = cnt >> 2;
#pragma unroll 4
    for (int i = threadIdx.x; i < nvec; i += 256) {
        const float4 x = v4[i];
        const float xx[4] = {x.x, x.y, x.z, x.w};
#pragma unroll
        for (int e = 0; e < 4; e++)
            atomicAdd(&sh[__float_as_uint(fabsf(xx[e] - med)) >> 20], 1);
    }
    for (int i = (nvec << 2) + threadIdx.x; i < cnt; i += 256)
        atomicAdd(&sh[__float_as_uint(fabsf(v[i] - med)) >> 20], 1);
    __syncthreads();
    for (int i = threadIdx.x; i < 2048; i += 256)
        if (sh[i]) atomicAdd(&g_mhist0[s][i], sh[i]);
}

__global__ void k8_mscan0() {
    const int s = blockIdx.x;
    if (g_n[s] <= 0) return;
    scan_find_one<2048>(g_mhist0[s], &g_mprefix[s], &g_mrem[s], 0);
}

__global__ void __launch_bounds__(256) k9_mref1() {
    const int s = blockIdx.y, b = blockIdx.x;
    const float med = g_med[s];
    const unsigned pf = g_mprefix[s];
    const int cnt = g_bcnt[s][b];
    const float* v = g_cmp + (size_t)s * S + (size_t)b * REG;
    const float4* v4 = reinterpret_cast<const float4*>(v);
    const int nvec = cnt >> 2;
#pragma unroll 4
    for (int i = threadIdx.x; i < nvec; i += 256) {
        const float4 x = v4[i];
        const float xx[4] = {x.x, x.y, x.z, x.w};
#pragma unroll
        for (int e = 0; e < 4; e++) {
            unsigned u = __float_as_uint(fabsf(xx[e] - med));
            if ((u >> 20) == pf) atomicAdd(&g_mhist1[s][(u >> 8) & 0xFFF], 1);
        }
    }
    for (int i = (nvec << 2) + threadIdx.x; i < cnt; i += 256) {
        unsigned u = __float_as_uint(fabsf(v[i] - med));
        if ((u >> 20) == pf) atomicAdd(&g_mhist1[s][(u >> 8) & 0xFFF], 1);
    }
}

__global__ void k10_mscan1() {
    const int s = blockIdx.x;
    if (g_n[s] <= 0) return;
    scan_find_one<4096>(g_mhist1[s], &g_mprefix[s], &g_mrem[s], 12);
}

__global__ void __launch_bounds__(256) k11_mref2() {
    const int s = blockIdx.y, b = blockIdx.x;
    const float med = g_med[s];
    const unsigned pf = g_mprefix[s];   // 24-bit
    const int cnt = g_bcnt[s][b];
    const float* v = g_cmp + (size_t)s * S + (size_t)b * REG;
    const float4* v4 = reinterpret_cast<const float4*>(v);
    const int nvec = cnt >> 2;
#pragma unroll 4
    for (int i = threadIdx.x; i < nvec; i += 256) {
        const float4 x = v4[i];
        const float xx[4] = {x.x, x.y, x.z, x.w};
#pragma unroll
        for (int e = 0; e < 4; e++) {
            unsigned u = __float_as_uint(fabsf(xx[e] - med));
            if ((u >> 8) == pf) atomicAdd(&g_mhist2[s][u & 0xFF], 1);
        }
    }
    for (int i = (nvec << 2) + threadIdx.x; i < cnt; i += 256) {
        unsigned u = __float_as_uint(fabsf(v[i] - med));
        if ((u >> 8) == pf) atomicAdd(&g_mhist2[s][u & 0xFF], 1);
    }
}

// ---------------- K12: final per-sample scalars + num_masked ----------------
__global__ void k12_final() {
    const int tid = threadIdx.x;  // 32 threads
    if (tid < B) {
        const int s = tid, n = g_n[s];
        float mad = 0.0f;
        if (n > 0) {
            int r = g_mrem[s], cum = 0;
            unsigned pf = g_mprefix[s];
            const int* h = g_mhist2[s];
            for (int b2 = 0; b2 < 256; b2++) {
                int c = h[b2];
                if (r < cum + c) { mad = __uint_as_float((pf << 8) | (unsigned)b2); break; }
                cum += c;
            }
        }
        float scaled = 1.4826f * mad;
        float iqr = fmaxf((g_q75[s] - g_q25[s]) / 1.35f, 1e-6f);
        float fm = (scaled < 0.1f) ? iqr : scaled;
        if (n <= 0) fm = 1.0f;
        int dn = (n > 0) && (fm > 0.1f);
        g_scale[s] = dn ? (1.0f / fm) : 1.0f;   // (p-med)/fm - (t-med)/fm == (p-t)/fm
    }
    if (tid == 0) {
        double nm = (double)B * (double)S;      // binary mask: sum(mask) = total - visible
        for (int s2 = 0; s2 < B; s2++) nm -= (double)g_n[s2];
        g_nmask = nm;
    }
}

// ---------------- K13: masked-MSE using visbits (no mask read) ----------------
// grid (512, B), block 256.
__global__ void __launch_bounds__(256) k13_loss(const float* __restrict__ pred,
                                                const float* __restrict__ tgt) {
    const int s = blockIdx.y;
    const float sc = g_scale[s];
    const size_t off = (size_t)s * S;
    const float* p = pred + off;
    const float* t = tgt + off;
    const unsigned* vb = g_visbits + s * WPS;
    const int base = blockIdx.x * 8192;
    float ls = 0.0f;
#pragma unroll
    for (int k = 0; k < 8; k++) {
        const int idx = base + k * 1024 + threadIdx.x * 4;
        const float4 pv = *reinterpret_cast<const float4*>(p + idx);
        const float4 tv = *reinterpret_cast<const float4*>(t + idx);
        const unsigned nib = (vb[idx >> 5] >> (idx & 31)) & 0xF;
        const float pp[4] = {pv.x, pv.y, pv.z, pv.w};
        const float tt[4] = {tv.x, tv.y, tv.z, tv.w};
#pragma unroll
        for (int j = 0; j < 4; j++) {
            float d = (pp[j] - tt[j]) * sc;
            float l = fminf(d * d, 100.0f);
            ls += ((nib >> j) & 1u) ? 0.0f : l;   // masked <=> not visible
        }
    }
    for (int o = 16; o; o >>= 1) ls += __shfl_down_sync(0xFFFFFFFFu, ls, o);
    __shared__ float wls[8];
    if ((threadIdx.x & 31) == 0) wls[threadIdx.x >> 5] = ls;
    __syncthreads();
    if (threadIdx.x == 0) {
        double a = 0.0;
        for (int i = 0; i < 8; i++) a += (double)wls[i];
        atomicAdd(&g_lsum, a);
    }
}

// ---------------- K14: write scalar output ----------------
__global__ void k14_out(float* out) {
    double nm = g_nmask;
    out[0] = (nm > 0.0) ? (float)(g_lsum / fmax(nm, 1.0)) : 0.0f;
}

// ---------------- launch ----------------
extern "C" void kernel_launch(void* const* d_in, const int* in_sizes, int n_in,
                              void* d_out, int out_size) {
    const float* pred = (const float*)d_in[0];
    const float* tgt  = (const float*)d_in[1];
    const float* msk  = (const float*)d_in[2];
    float* out = (float*)d_out;

    dim3 greg(NBLK, B), gloss(512, B);

    k0_zero<<<128, 256>>>();
    k1_compact<<<greg, 256>>>(tgt, msk);
    k2_setup<<<B, 256>>>();
    k3_ref1<<<greg, 256>>>();
    k4_scan1<<<B * NR, 256>>>();
    k5_ref2<<<greg, 256>>>();
    k6_vals<<<1, 256>>>();
    k7_mhist0<<<greg, 256>>>();
    k8_mscan0<<<B, 256>>>();
    k9_mref1<<<greg, 256>>>();
    k10_mscan1<<<B, 256>>>();
    k11_mref2<<<greg, 256>>>();
    k12_final<<<1, 32>>>();
    k13_loss<<<gloss, 256>>>(pred, tgt);
    k14_out<<<1, 1>>>(out);
}